// round 12
// baseline (speedup 1.0000x reference)
#include <cuda_runtime.h>
#include <cfloat>
#include <cstdint>

#define GV 8
#define KV 1024
#define DV 128
#define MV 16384
#define QN (MV*GV*DV)
#define NIDX (MV*GV)

__device__ float  g_c2[GV*KV];
__device__ __align__(256) float g_cbT[GV*DV*KV];  // [g][k][n]
__device__ double g_loss;
__device__ unsigned int g_cnt;

__device__ __forceinline__ void ffma2(unsigned long long& d,
                                      unsigned long long a,
                                      unsigned long long b) {
    asm volatile("fma.rn.f32x2 %0, %1, %2, %0;" : "+l"(d) : "l"(a), "l"(b));
}
__device__ __forceinline__ unsigned long long splat2(float x) {
    unsigned long long r; unsigned u = __float_as_uint(x);
    asm("mov.b64 %0, {%1, %1};" : "=l"(r) : "r"(u));
    return r;
}
__device__ __forceinline__ void unpack2(unsigned long long v, float& lo, float& hi) {
    unsigned a, b;
    asm("mov.b64 {%0, %1}, %2;" : "=r"(a), "=r"(b) : "l"(v));
    lo = __uint_as_float(a); hi = __uint_as_float(b);
}
__device__ __forceinline__ uint32_t smem_to_u32(const void* p) {
    uint32_t a;
    asm("{ .reg .u64 t; cvta.to.shared.u64 t, %1; cvt.u32.u64 %0, t; }" : "=r"(a) : "l"(p));
    return a;
}
__device__ __forceinline__ void cp16(uint32_t dst, const void* src) {
    asm volatile("cp.async.cg.shared.global [%0], [%1], 16;" :: "r"(dst), "l"(src) : "memory");
}
#define CP_COMMIT() asm volatile("cp.async.commit_group;" ::: "memory")
#define CP_WAIT0()  asm volatile("cp.async.wait_group 0;" ::: "memory")

// SMEM (bytes): A 32768 | B 2x32768 | x2 256 | midx 256 | wsum 32
#define SM_A    0
#define SM_B    32768
#define SM_X2   98304
#define SM_MIDX 98560
#define SM_WSUM 98816
#define SM_TOTAL 98848

// ---------- kernel 1: c2 + k-major transpose (R10-proven) ----------
__global__ void k_prep(const float* __restrict__ cb) {
    __shared__ float tile[32 * 129];
    if (blockIdx.x == 0 && threadIdx.x == 0) { g_loss = 0.0; g_cnt = 0u; }
    const int tid = threadIdx.x;
    const int g   = blockIdx.x >> 5;
    const int n0  = (blockIdx.x & 31) * 32;
    const float* src = cb + ((size_t)g * KV + n0) * DV;
    #pragma unroll
    for (int i = 0; i < 4; i++) {
        int u = tid + i * 256;
        int n = u >> 5, k4 = u & 31;
        float4 v = *(const float4*)(src + (size_t)n * DV + k4 * 4);
        float* d = &tile[n * 129 + k4 * 4];
        d[0] = v.x; d[1] = v.y; d[2] = v.z; d[3] = v.w;
    }
    __syncthreads();
    {
        int lane = tid & 31, w = tid >> 5;
        #pragma unroll
        for (int it = 0; it < 4; ++it) {
            int n = w * 4 + it;
            const float* row = &tile[n * 129 + lane * 4];   // scalar: odd rows not 16B-aligned
            float s = row[0] * row[0];
            s = fmaf(row[1], row[1], s);
            s = fmaf(row[2], row[2], s);
            s = fmaf(row[3], row[3], s);
            #pragma unroll
            for (int o = 16; o > 0; o >>= 1) s += __shfl_xor_sync(0xffffffffu, s, o);
            if (lane == 0) g_c2[g * KV + n0 + n] = s;
        }
    }
    float* dstg = g_cbT + (size_t)g * DV * KV + n0;
    #pragma unroll
    for (int i = 0; i < 16; i++) {
        int u = tid + i * 256;
        int k = u >> 5, n = u & 31;
        dstg[(size_t)k * KV + n] = tile[n * 129 + k];
    }
}

// ---------- kernel 2: FFMA2 GEMM + argmin + fused quantize/loss, occ=2 ----------
// CTA: 64 tokens x 1024 codes (16 chunks of 64). 256 threads, 4x4 tile.
__global__ void __launch_bounds__(256, 2)
k_main(const float* __restrict__ x, const float* __restrict__ cb,
       float* __restrict__ outq, float* __restrict__ losses,
       float* __restrict__ out_idx_f) {
    extern __shared__ float sm[];
    float* As   = sm;                              // [k][64]
    float* x2s  = (float*)((char*)sm + SM_X2);
    int*   sidx = (int*)((char*)sm + SM_MIDX);
    float* wsum = (float*)((char*)sm + SM_WSUM);
    const uint32_t sb = smem_to_u32(sm);

    const int tid = threadIdx.x;
    const int g   = blockIdx.y;
    const int m0  = blockIdx.x * 64;
    const int row_t = tid >> 4;          // 0..15 -> rows row_t*4..+3
    const int col_t = tid & 15;          // 0..15 -> cols col_t*4..+3

    // A tile transposed (k-major), 64 tokens
    #pragma unroll
    for (int i = 0; i < 8; i++) {
        int u = tid + i * 256;            // 0..2047
        int m  = u & 63;
        int kv = u >> 6;                  // 0..31
        float4 v = *(const float4*)(x + (size_t)(m0 + m) * (GV * DV) + g * DV + kv * 4);
        float* dst = As + (kv * 4) * 64 + m;
        dst[0]  = v.x;
        dst[64] = v.y;
        dst[128] = v.z;
        dst[192] = v.w;
    }

    // prefetch B chunk 0 (64 codes)
    const char* srcg = (const char*)(g_cbT + (size_t)g * DV * KV);
    #pragma unroll
    for (int i = 0; i < 8; i++) {
        int u = tid + i * 256;            // 0..2047
        int k  = u >> 4;                  // 0..127
        int n4 = u & 15;                  // 16B unit within 64 cols
        cp16(sb + SM_B + (uint32_t)(k * 256 + n4 * 16),
             srcg + (size_t)k * 4096 + n4 * 16);
    }
    CP_COMMIT();
    __syncthreads();

    if (tid < 64) {
        float s = 0.f;
        #pragma unroll 8
        for (int k = 0; k < 128; k++) { float a = As[k * 64 + tid]; s = fmaf(a, a, s); }
        x2s[tid] = s;
    }
    __syncthreads();

    float rx2[4];
    #pragma unroll
    for (int i = 0; i < 4; i++) rx2[i] = x2s[row_t * 4 + i];

    float best[4]; int bidx[4];
    #pragma unroll
    for (int i = 0; i < 4; i++) { best[i] = FLT_MAX; bidx[i] = 0; }

    const float* c2g = g_c2 + g * KV;

    for (int ch = 0; ch < 16; ++ch) {
        CP_WAIT0();
        __syncthreads();
        if (ch < 15) {
            uint32_t dst = sb + SM_B + (uint32_t)(((ch + 1) & 1) * 32768);
            const char* src = srcg + (size_t)(ch + 1) * 256;
            #pragma unroll
            for (int i = 0; i < 8; i++) {
                int u = tid + i * 256;
                int k  = u >> 4;
                int n4 = u & 15;
                cp16(dst + (uint32_t)(k * 256 + n4 * 16),
                     src + (size_t)k * 4096 + n4 * 16);
            }
            CP_COMMIT();
        }
        const float* Cs = (const float*)((char*)sm + SM_B + (ch & 1) * 32768);

        unsigned long long acc[2][4];
        #pragma unroll
        for (int p = 0; p < 2; p++)
            #pragma unroll
            for (int j = 0; j < 4; j++) acc[p][j] = 0ULL;

        #pragma unroll 8
        for (int k = 0; k < 128; k++) {
            ulonglong2 a = *(const ulonglong2*)(As + k * 64 + row_t * 4); // rows (0,1),(2,3)
            float4 c = *(const float4*)(Cs + k * 64 + col_t * 4);
            unsigned long long cj[4];
            cj[0] = splat2(c.x); cj[1] = splat2(c.y);
            cj[2] = splat2(c.z); cj[3] = splat2(c.w);
            #pragma unroll
            for (int j = 0; j < 4; j++) {
                ffma2(acc[0][j], a.x, cj[j]);
                ffma2(acc[1][j], a.y, cj[j]);
            }
        }

        // dist = (x2 - 2*xc) + c2, same rounding as reference
        #pragma unroll
        for (int j = 0; j < 4; j++) {
            int n = ch * 64 + col_t * 4 + j;
            float cc = __ldg(c2g + n);
            #pragma unroll
            for (int p = 0; p < 2; p++) {
                float lo, hi; unpack2(acc[p][j], lo, hi);
                float d0 = __fadd_rn(__fsub_rn(rx2[2*p],   __fmul_rn(2.0f, lo)), cc);
                float d1 = __fadd_rn(__fsub_rn(rx2[2*p+1], __fmul_rn(2.0f, hi)), cc);
                if (d0 < best[2*p])   { best[2*p]   = d0; bidx[2*p]   = n; }
                if (d1 < best[2*p+1]) { best[2*p+1] = d1; bidx[2*p+1] = n; }
            }
        }
    }

    // merge across 16 col lanes
    #pragma unroll
    for (int off = 1; off < 16; off <<= 1) {
        #pragma unroll
        for (int i = 0; i < 4; i++) {
            float ov = __shfl_xor_sync(0xffffffffu, best[i], off);
            int   oi = __shfl_xor_sync(0xffffffffu, bidx[i], off);
            if (ov < best[i] || (ov == best[i] && oi < bidx[i])) {
                best[i] = ov; bidx[i] = oi;
            }
        }
    }
    if (col_t == 0) {
        #pragma unroll
        for (int i = 0; i < 4; i++) {
            int m = m0 + row_t * 4 + i;
            sidx[row_t * 4 + i]   = bidx[i];
            out_idx_f[m * GV + g] = (float)bidx[i];
        }
    }
    __syncthreads();

    // fused quantize + loss (R10-proven formulas)
    const float* cbg = cb + (size_t)g * KV * DV;
    float lacc = 0.f;
    #pragma unroll
    for (int i = 0; i < 8; i++) {
        int u = tid + i * 256;            // 0..2047
        int m  = u >> 5;                  // 0..63
        int k4 = u & 31;
        int idx = sidx[m];
        const float4 xv = *(const float4*)(x + (size_t)(m0 + m) * (GV * DV) + g * DV + k4 * 4);
        const float4 qv = __ldg((const float4*)(cbg + (size_t)idx * DV + k4 * 4));
        float4 o;
        o.x = __fadd_rn(xv.x, __fsub_rn(qv.x, xv.x));
        o.y = __fadd_rn(xv.y, __fsub_rn(qv.y, xv.y));
        o.z = __fadd_rn(xv.z, __fsub_rn(qv.z, xv.z));
        o.w = __fadd_rn(xv.w, __fsub_rn(qv.w, xv.w));
        *(float4*)(outq + (size_t)(m0 + m) * (GV * DV) + g * DV + k4 * 4) = o;
        float d = __fsub_rn(xv.x, qv.x); lacc = fmaf(d, d, lacc);
        d = __fsub_rn(xv.y, qv.y); lacc = fmaf(d, d, lacc);
        d = __fsub_rn(xv.z, qv.z); lacc = fmaf(d, d, lacc);
        d = __fsub_rn(xv.w, qv.w); lacc = fmaf(d, d, lacc);
    }
    #pragma unroll
    for (int o = 16; o > 0; o >>= 1) lacc += __shfl_xor_sync(0xffffffffu, lacc, o);
    if ((tid & 31) == 0) wsum[tid >> 5] = lacc;
    __syncthreads();
    if (tid == 0) {
        double t = 0.0;
        #pragma unroll
        for (int i = 0; i < 8; i++) t += (double)wsum[i];
        atomicAdd(&g_loss, t);
        __threadfence();
        unsigned int done = atomicAdd(&g_cnt, 1u);
        if (done == (unsigned int)(gridDim.x * gridDim.y) - 1u) {
            float L = (float)(g_loss * (1.0 / (double)QN));
            losses[0] = L;
            losses[1] = L;
        }
    }
}

extern "C" void kernel_launch(void* const* d_in, const int* in_sizes, int n_in,
                              void* d_out, int out_size) {
    (void)in_sizes; (void)n_in; (void)out_size;
    const float* x  = (const float*)d_in[0];
    const float* cb = (const float*)d_in[1];
    float* out    = (float*)d_out;
    float* outq   = out;
    float* losses = out + QN;
    float* outidx = out + QN + 2;

    k_prep<<<256, 256>>>(cb);
    cudaFuncSetAttribute(k_main, cudaFuncAttributeMaxDynamicSharedMemorySize, SM_TOTAL);
    k_main<<<dim3(MV / 64, GV), 256, SM_TOTAL>>>(x, cb, outq, losses, outidx);
}

// round 13
// speedup vs baseline: 1.1345x; 1.1345x over previous
#include <cuda_runtime.h>
#include <cfloat>
#include <cstdint>

// Problem constants
#define BV 8
#define TV 2048
#define GV 8
#define KV 1024
#define DV 128
#define MV (BV*TV)            // 16384 tokens
#define QN (MV*GV*DV)         // 16777216 quantized elements
#define NIDX (MV*GV)          // 131072 indices

// Scratch (static device globals)
__device__ float  g_c2[GV*KV];
__device__ __align__(256) float g_cbT[GV*DV*KV];  // [g][k][n] k-major transposed codebook
__device__ double g_loss;
__device__ unsigned int g_cnt;

// ---------- packed fp32x2 helpers ----------
__device__ __forceinline__ void ffma2(unsigned long long& d,
                                      unsigned long long a,
                                      unsigned long long b) {
    asm volatile("fma.rn.f32x2 %0, %1, %2, %0;" : "+l"(d) : "l"(a), "l"(b));
}
__device__ __forceinline__ unsigned long long splat2(float x) {
    unsigned long long r; unsigned u = __float_as_uint(x);
    asm("mov.b64 %0, {%1, %1};" : "=l"(r) : "r"(u));
    return r;
}
__device__ __forceinline__ void unpack2(unsigned long long v, float& lo, float& hi) {
    unsigned a, b;
    asm("mov.b64 {%0, %1}, %2;" : "=r"(a), "=r"(b) : "l"(v));
    lo = __uint_as_float(a); hi = __uint_as_float(b);
}
__device__ __forceinline__ uint32_t smem_to_u32(const void* p) {
    uint32_t a;
    asm("{ .reg .u64 t; cvta.to.shared.u64 t, %1; cvt.u32.u64 %0, t; }" : "=r"(a) : "l"(p));
    return a;
}
__device__ __forceinline__ void cp16(uint32_t dst, const void* src) {
    asm volatile("cp.async.cg.shared.global [%0], [%1], 16;" :: "r"(dst), "l"(src) : "memory");
}
#define CP_COMMIT() asm volatile("cp.async.commit_group;" ::: "memory")
#define CP_WAIT0()  asm volatile("cp.async.wait_group 0;" ::: "memory")

// SMEM layout (bytes) for k_main
#define SM_A    0          // 65536: As[k][m] fp32 k-major
#define SM_B    65536      // 2 x 65536: Cs[k][n] fp32 k-major, double buffered
#define SM_X2   196608     // 512
#define SM_MIDX 197120     // 512 (winning index broadcast)
#define SM_WSUM 197632     // 32  (loss partials)
#define SM_TOTAL 197664

// ---------- kernel 1: c2 + coalesced k-major transpose + counter reset ----------
__global__ void k_prep(const float* __restrict__ cb) {
    __shared__ float tile[32 * 129];   // [code][k], pad 129 for conflict-free transpose
    if (blockIdx.x == 0 && threadIdx.x == 0) { g_loss = 0.0; g_cnt = 0u; }

    const int tid = threadIdx.x;
    const int g   = blockIdx.x >> 5;          // 0..7
    const int n0  = (blockIdx.x & 31) * 32;   // code tile base

    const float* src = cb + ((size_t)g * KV + n0) * DV;
    #pragma unroll
    for (int i = 0; i < 4; i++) {
        int u = tid + i * 256;
        int n  = u >> 5;
        int k4 = u & 31;
        float4 v = *(const float4*)(src + (size_t)n * DV + k4 * 4);
        float* d = &tile[n * 129 + k4 * 4];
        d[0] = v.x; d[1] = v.y; d[2] = v.z; d[3] = v.w;
    }
    __syncthreads();

    // c2: scalar smem reads (odd rows not 16B-aligned — R9 lesson)
    {
        int lane = tid & 31, w = tid >> 5;
        #pragma unroll
        for (int it = 0; it < 4; ++it) {
            int n = w * 4 + it;
            const float* row = &tile[n * 129 + lane * 4];
            float s = row[0] * row[0];
            s = fmaf(row[1], row[1], s);
            s = fmaf(row[2], row[2], s);
            s = fmaf(row[3], row[3], s);
            #pragma unroll
            for (int o = 16; o > 0; o >>= 1) s += __shfl_xor_sync(0xffffffffu, s, o);
            if (lane == 0) g_c2[g * KV + n0 + n] = s;
        }
    }

    float* dstg = g_cbT + (size_t)g * DV * KV + n0;
    #pragma unroll
    for (int i = 0; i < 16; i++) {
        int u = tid + i * 256;
        int k = u >> 5, n = u & 31;
        dstg[(size_t)k * KV + n] = tile[n * 129 + k];
    }
}

// ---------- kernel 2: exact fp32 FFMA2 GEMM + argmin + fused quantize/loss ----------
// CTA: 128 tokens x all 1024 codes for one group. 256 threads, 8x8 thread tile.
__global__ void __launch_bounds__(256, 1)
k_main(const float* __restrict__ x, const float* __restrict__ cb,
       float* __restrict__ outq, float* __restrict__ losses,
       float* __restrict__ out_idx_f) {
    extern __shared__ float sm[];
    float* As   = sm;                          // 16384 floats
    float* x2s  = (float*)((char*)sm + SM_X2);
    int*   sidx = (int*)((char*)sm + SM_MIDX);
    float* wsum = (float*)((char*)sm + SM_WSUM);
    const uint32_t sb = smem_to_u32(sm);

    const int tid = threadIdx.x;
    const int g   = blockIdx.y;
    const int m0  = blockIdx.x * 128;

    // Load A tile transposed (k-major). lane-over-m => conflict-free STS.
    #pragma unroll
    for (int i = 0; i < 16; i++) {
        int idx = tid + i * 256;          // 0..4095
        int m  = idx & 127;
        int kv = idx >> 7;                // 0..31
        float4 v = *(const float4*)(x + (size_t)(m0 + m) * (GV * DV) + g * DV + kv * 4);
        float* dst = As + (kv * 4) * 128 + m;
        dst[0]   = v.x;
        dst[128] = v.y;
        dst[256] = v.z;
        dst[384] = v.w;
    }

    // prefetch B chunk 0
    const char* srcg = (const char*)(g_cbT + (size_t)g * DV * KV);
    {
        #pragma unroll
        for (int i = 0; i < 16; i++) {
            int u = tid + i * 256;
            int k  = u >> 5;
            int n4 = u & 31;
            cp16(sb + SM_B + (uint32_t)(k * 512 + n4 * 16),
                 srcg + (size_t)k * 4096 + n4 * 16);
        }
        CP_COMMIT();
    }
    __syncthreads();

    // x2 per row
    if (tid < 128) {
        float s = 0.f;
        #pragma unroll 8
        for (int k = 0; k < 128; k++) { float a = As[k * 128 + tid]; s = fmaf(a, a, s); }
        x2s[tid] = s;
    }
    __syncthreads();

    const int row_t = tid >> 4;
    const int col_t = tid & 15;

    float rx2[8];
    #pragma unroll
    for (int i = 0; i < 8; i++) rx2[i] = x2s[row_t * 8 + i];

    float best[8]; int bidx[8];
    #pragma unroll
    for (int i = 0; i < 8; i++) { best[i] = FLT_MAX; bidx[i] = 0; }

    const float* c2g = g_c2 + g * KV;

    for (int n0 = 0; n0 < KV; n0 += 128) {
        CP_WAIT0();
        __syncthreads();
        const int ch = n0 >> 7;
        if (n0 + 128 < KV) {
            uint32_t dst = sb + SM_B + (uint32_t)(((ch + 1) & 1) * 65536);
            const char* src = srcg + (size_t)(n0 + 128) * 4;
            #pragma unroll
            for (int i = 0; i < 16; i++) {
                int u = tid + i * 256;
                int k  = u >> 5;
                int n4 = u & 31;
                cp16(dst + (uint32_t)(k * 512 + n4 * 16),
                     src + (size_t)k * 4096 + n4 * 16);
            }
            CP_COMMIT();
        }
        const float* Cs = sm + 16384 + (ch & 1) * 16384;

        unsigned long long acc[4][8];
        #pragma unroll
        for (int p = 0; p < 4; p++)
            #pragma unroll
            for (int j = 0; j < 8; j++) acc[p][j] = 0ULL;

        #pragma unroll 8
        for (int k = 0; k < 128; k++) {
            const float* ar = As + k * 128 + row_t * 8;
            ulonglong2 a01 = *(const ulonglong2*)ar;
            ulonglong2 a23 = *(const ulonglong2*)(ar + 4);
            const float* cr = Cs + k * 128 + col_t * 8;
            float4 c0 = *(const float4*)cr;
            float4 c1 = *(const float4*)(cr + 4);
            unsigned long long cj[8];
            cj[0] = splat2(c0.x); cj[1] = splat2(c0.y);
            cj[2] = splat2(c0.z); cj[3] = splat2(c0.w);
            cj[4] = splat2(c1.x); cj[5] = splat2(c1.y);
            cj[6] = splat2(c1.z); cj[7] = splat2(c1.w);
            #pragma unroll
            for (int j = 0; j < 8; j++) {
                ffma2(acc[0][j], a01.x, cj[j]);
                ffma2(acc[1][j], a01.y, cj[j]);
                ffma2(acc[2][j], a23.x, cj[j]);
                ffma2(acc[3][j], a23.y, cj[j]);
            }
        }

        #pragma unroll
        for (int j = 0; j < 8; j++) {
            int n = n0 + col_t * 8 + j;
            float cc = __ldg(c2g + n);
            #pragma unroll
            for (int p = 0; p < 4; p++) {
                float lo, hi; unpack2(acc[p][j], lo, hi);
                float d0 = __fadd_rn(__fsub_rn(rx2[2*p],   __fmul_rn(2.0f, lo)), cc);
                float d1 = __fadd_rn(__fsub_rn(rx2[2*p+1], __fmul_rn(2.0f, hi)), cc);
                if (d0 < best[2*p])   { best[2*p]   = d0; bidx[2*p]   = n; }
                if (d1 < best[2*p+1]) { best[2*p+1] = d1; bidx[2*p+1] = n; }
            }
        }
    }

    #pragma unroll
    for (int off = 1; off < 16; off <<= 1) {
        #pragma unroll
        for (int i = 0; i < 8; i++) {
            float ov = __shfl_xor_sync(0xffffffffu, best[i], off);
            int   oi = __shfl_xor_sync(0xffffffffu, bidx[i], off);
            if (ov < best[i] || (ov == best[i] && oi < bidx[i])) {
                best[i] = ov; bidx[i] = oi;
            }
        }
    }
    if (col_t == 0) {
        #pragma unroll
        for (int i = 0; i < 8; i++) {
            int m = m0 + row_t * 8 + i;
            sidx[row_t * 8 + i]   = bidx[i];
            out_idx_f[m * GV + g] = (float)bidx[i];
        }
    }
    __syncthreads();

    // fused quantize + loss
    const float* cbg = cb + (size_t)g * KV * DV;
    float lacc = 0.f;
    #pragma unroll
    for (int i = 0; i < 16; i++) {
        int u = tid + i * 256;
        int m  = u >> 5;
        int k4 = u & 31;
        int idx = sidx[m];
        const float4 xv = *(const float4*)(x + (size_t)(m0 + m) * (GV * DV) + g * DV + k4 * 4);
        const float4 qv = __ldg((const float4*)(cbg + (size_t)idx * DV + k4 * 4));
        float4 o;
        o.x = __fadd_rn(xv.x, __fsub_rn(qv.x, xv.x));
        o.y = __fadd_rn(xv.y, __fsub_rn(qv.y, xv.y));
        o.z = __fadd_rn(xv.z, __fsub_rn(qv.z, xv.z));
        o.w = __fadd_rn(xv.w, __fsub_rn(qv.w, xv.w));
        *(float4*)(outq + (size_t)(m0 + m) * (GV * DV) + g * DV + k4 * 4) = o;
        float d = __fsub_rn(xv.x, qv.x); lacc = fmaf(d, d, lacc);
        d = __fsub_rn(xv.y, qv.y); lacc = fmaf(d, d, lacc);
        d = __fsub_rn(xv.z, qv.z); lacc = fmaf(d, d, lacc);
        d = __fsub_rn(xv.w, qv.w); lacc = fmaf(d, d, lacc);
    }
    #pragma unroll
    for (int o = 16; o > 0; o >>= 1) lacc += __shfl_xor_sync(0xffffffffu, lacc, o);
    if ((tid & 31) == 0) wsum[tid >> 5] = lacc;
    __syncthreads();
    if (tid == 0) {
        double t = 0.0;
        #pragma unroll
        for (int i = 0; i < 8; i++) t += (double)wsum[i];
        atomicAdd(&g_loss, t);
        __threadfence();
        unsigned int done = atomicAdd(&g_cnt, 1u);
        if (done == (unsigned int)(gridDim.x * gridDim.y) - 1u) {
            float L = (float)(g_loss * (1.0 / (double)QN));
            losses[0] = L;
            losses[1] = L;
        }
    }
}

extern "C" void kernel_launch(void* const* d_in, const int* in_sizes, int n_in,
                              void* d_out, int out_size) {
    (void)in_sizes; (void)n_in; (void)out_size;
    const float* x  = (const float*)d_in[0];
    const float* cb = (const float*)d_in[1];
    float* out    = (float*)d_out;
    float* outq   = out;
    float* losses = out + QN;
    float* outidx = out + QN + 2;

    k_prep<<<256, 256>>>(cb);
    cudaFuncSetAttribute(k_main, cudaFuncAttributeMaxDynamicSharedMemorySize, SM_TOTAL);
    k_main<<<dim3(MV / 128, GV), 256, SM_TOTAL>>>(x, cb, outq, losses, outidx);
}

// round 14
// speedup vs baseline: 1.1379x; 1.0030x over previous
#include <cuda_runtime.h>
#include <cfloat>
#include <cstdint>

// Problem constants
#define BV 8
#define TV 2048
#define GV 8
#define KV 1024
#define DV 128
#define MV (BV*TV)            // 16384 tokens
#define QN (MV*GV*DV)         // 16777216 quantized elements
#define NIDX (MV*GV)          // 131072 indices

// Scratch (static device globals)
__device__ float  g_c2[GV*KV];
__device__ __align__(256) float g_cbT[GV*DV*KV];  // [g][k][n] k-major transposed codebook
__device__ double g_loss;
__device__ unsigned int g_cnt;

// ---------- packed fp32x2 helpers ----------
__device__ __forceinline__ void ffma2(unsigned long long& d,
                                      unsigned long long a,
                                      unsigned long long b) {
    asm volatile("fma.rn.f32x2 %0, %1, %2, %0;" : "+l"(d) : "l"(a), "l"(b));
}
__device__ __forceinline__ unsigned long long splat2(float x) {
    unsigned long long r; unsigned u = __float_as_uint(x);
    asm("mov.b64 %0, {%1, %1};" : "=l"(r) : "r"(u));
    return r;
}
__device__ __forceinline__ void unpack2(unsigned long long v, float& lo, float& hi) {
    unsigned a, b;
    asm("mov.b64 {%0, %1}, %2;" : "=r"(a), "=r"(b) : "l"(v));
    lo = __uint_as_float(a); hi = __uint_as_float(b);
}
__device__ __forceinline__ uint32_t smem_to_u32(const void* p) {
    uint32_t a;
    asm("{ .reg .u64 t; cvta.to.shared.u64 t, %1; cvt.u32.u64 %0, t; }" : "=r"(a) : "l"(p));
    return a;
}
__device__ __forceinline__ void cp16(uint32_t dst, const void* src) {
    asm volatile("cp.async.cg.shared.global [%0], [%1], 16;" :: "r"(dst), "l"(src) : "memory");
}
#define CP_COMMIT() asm volatile("cp.async.commit_group;" ::: "memory")
#define CP_WAIT0()  asm volatile("cp.async.wait_group 0;" ::: "memory")

// SMEM layout (bytes) for k_main
#define SM_A    0          // 65536: As[k][m] fp32 k-major
#define SM_B    65536      // 2 x 65536: Cs[k][n] fp32 k-major, double buffered
#define SM_X2   196608     // 512
#define SM_MIDX 197120     // 512 (winning index broadcast)
#define SM_WSUM 197632     // 32  (loss partials)
#define SM_TOTAL 197664

// ---------- kernel 1: c2 + coalesced k-major transpose + counter reset ----------
__global__ void k_prep(const float* __restrict__ cb) {
    __shared__ float tile[32 * 129];   // [code][k], pad 129 for conflict-free transpose
    if (blockIdx.x == 0 && threadIdx.x == 0) { g_loss = 0.0; g_cnt = 0u; }

    const int tid = threadIdx.x;
    const int g   = blockIdx.x >> 5;          // 0..7
    const int n0  = (blockIdx.x & 31) * 32;   // code tile base

    const float* src = cb + ((size_t)g * KV + n0) * DV;
    #pragma unroll
    for (int i = 0; i < 4; i++) {
        int u = tid + i * 256;
        int n  = u >> 5;
        int k4 = u & 31;
        float4 v = *(const float4*)(src + (size_t)n * DV + k4 * 4);
        float* d = &tile[n * 129 + k4 * 4];
        d[0] = v.x; d[1] = v.y; d[2] = v.z; d[3] = v.w;
    }
    __syncthreads();

    // c2: scalar smem reads (odd rows not 16B-aligned — R9 lesson)
    {
        int lane = tid & 31, w = tid >> 5;
        #pragma unroll
        for (int it = 0; it < 4; ++it) {
            int n = w * 4 + it;
            const float* row = &tile[n * 129 + lane * 4];
            float s = row[0] * row[0];
            s = fmaf(row[1], row[1], s);
            s = fmaf(row[2], row[2], s);
            s = fmaf(row[3], row[3], s);
            #pragma unroll
            for (int o = 16; o > 0; o >>= 1) s += __shfl_xor_sync(0xffffffffu, s, o);
            if (lane == 0) g_c2[g * KV + n0 + n] = s;
        }
    }

    float* dstg = g_cbT + (size_t)g * DV * KV + n0;
    #pragma unroll
    for (int i = 0; i < 16; i++) {
        int u = tid + i * 256;
        int k = u >> 5, n = u & 31;
        dstg[(size_t)k * KV + n] = tile[n * 129 + k];
    }
}

// ---------- kernel 2: exact fp32 FFMA2 GEMM + argmin + fused quantize/loss ----------
// CTA: 128 tokens x all 1024 codes for one group. 256 threads, 8x8 thread tile.
__global__ void __launch_bounds__(256, 1)
k_main(const float* __restrict__ x, const float* __restrict__ cb,
       float* __restrict__ outq, float* __restrict__ losses,
       float* __restrict__ out_idx_f) {
    extern __shared__ float sm[];
    float* As   = sm;                          // 16384 floats
    float* x2s  = (float*)((char*)sm + SM_X2);
    int*   sidx = (int*)((char*)sm + SM_MIDX);
    float* wsum = (float*)((char*)sm + SM_WSUM);
    const uint32_t sb = smem_to_u32(sm);

    const int tid = threadIdx.x;
    const int g   = blockIdx.y;
    const int m0  = blockIdx.x * 128;

    // Load A tile transposed (k-major). lane-over-m => conflict-free STS.
    #pragma unroll
    for (int i = 0; i < 16; i++) {
        int idx = tid + i * 256;          // 0..4095
        int m  = idx & 127;
        int kv = idx >> 7;                // 0..31
        float4 v = *(const float4*)(x + (size_t)(m0 + m) * (GV * DV) + g * DV + kv * 4);
        float* dst = As + (kv * 4) * 128 + m;
        dst[0]   = v.x;
        dst[128] = v.y;
        dst[256] = v.z;
        dst[384] = v.w;
    }

    // prefetch B chunk 0
    const char* srcg = (const char*)(g_cbT + (size_t)g * DV * KV);
    {
        #pragma unroll
        for (int i = 0; i < 16; i++) {
            int u = tid + i * 256;
            int k  = u >> 5;
            int n4 = u & 31;
            cp16(sb + SM_B + (uint32_t)(k * 512 + n4 * 16),
                 srcg + (size_t)k * 4096 + n4 * 16);
        }
        CP_COMMIT();
    }
    __syncthreads();

    // x2 per row
    if (tid < 128) {
        float s = 0.f;
        #pragma unroll 8
        for (int k = 0; k < 128; k++) { float a = As[k * 128 + tid]; s = fmaf(a, a, s); }
        x2s[tid] = s;
    }
    __syncthreads();

    const int row_t = tid >> 4;
    const int col_t = tid & 15;

    float rx2[8];
    #pragma unroll
    for (int i = 0; i < 8; i++) rx2[i] = x2s[row_t * 8 + i];

    float best[8]; int bidx[8];
    #pragma unroll
    for (int i = 0; i < 8; i++) { best[i] = FLT_MAX; bidx[i] = 0; }

    const float* c2g = g_c2 + g * KV;

    for (int n0 = 0; n0 < KV; n0 += 128) {
        CP_WAIT0();
        __syncthreads();
        const int ch = n0 >> 7;
        if (n0 + 128 < KV) {
            uint32_t dst = sb + SM_B + (uint32_t)(((ch + 1) & 1) * 65536);
            const char* src = srcg + (size_t)(n0 + 128) * 4;
            #pragma unroll
            for (int i = 0; i < 16; i++) {
                int u = tid + i * 256;
                int k  = u >> 5;
                int n4 = u & 31;
                cp16(dst + (uint32_t)(k * 512 + n4 * 16),
                     src + (size_t)k * 4096 + n4 * 16);
            }
            CP_COMMIT();
        }
        const float* Cs = sm + 16384 + (ch & 1) * 16384;

        unsigned long long acc[4][8];
        #pragma unroll
        for (int p = 0; p < 4; p++)
            #pragma unroll
            for (int j = 0; j < 8; j++) acc[p][j] = 0ULL;

        #pragma unroll 8
        for (int k = 0; k < 128; k++) {
            const float* ar = As + k * 128 + row_t * 8;
            ulonglong2 a01 = *(const ulonglong2*)ar;
            ulonglong2 a23 = *(const ulonglong2*)(ar + 4);
            const float* cr = Cs + k * 128 + col_t * 8;
            float4 c0 = *(const float4*)cr;
            float4 c1 = *(const float4*)(cr + 4);
            unsigned long long cj[8];
            cj[0] = splat2(c0.x); cj[1] = splat2(c0.y);
            cj[2] = splat2(c0.z); cj[3] = splat2(c0.w);
            cj[4] = splat2(c1.x); cj[5] = splat2(c1.y);
            cj[6] = splat2(c1.z); cj[7] = splat2(c1.w);
            #pragma unroll
            for (int j = 0; j < 8; j++) {
                ffma2(acc[0][j], a01.x, cj[j]);
                ffma2(acc[1][j], a01.y, cj[j]);
                ffma2(acc[2][j], a23.x, cj[j]);
                ffma2(acc[3][j], a23.y, cj[j]);
            }
        }

        #pragma unroll
        for (int j = 0; j < 8; j++) {
            int n = n0 + col_t * 8 + j;
            float cc = __ldg(c2g + n);
            #pragma unroll
            for (int p = 0; p < 4; p++) {
                float lo, hi; unpack2(acc[p][j], lo, hi);
                float d0 = __fadd_rn(__fsub_rn(rx2[2*p],   __fmul_rn(2.0f, lo)), cc);
                float d1 = __fadd_rn(__fsub_rn(rx2[2*p+1], __fmul_rn(2.0f, hi)), cc);
                if (d0 < best[2*p])   { best[2*p]   = d0; bidx[2*p]   = n; }
                if (d1 < best[2*p+1]) { best[2*p+1] = d1; bidx[2*p+1] = n; }
            }
        }
    }

    #pragma unroll
    for (int off = 1; off < 16; off <<= 1) {
        #pragma unroll
        for (int i = 0; i < 8; i++) {
            float ov = __shfl_xor_sync(0xffffffffu, best[i], off);
            int   oi = __shfl_xor_sync(0xffffffffu, bidx[i], off);
            if (ov < best[i] || (ov == best[i] && oi < bidx[i])) {
                best[i] = ov; bidx[i] = oi;
            }
        }
    }
    if (col_t == 0) {
        #pragma unroll
        for (int i = 0; i < 8; i++) {
            int m = m0 + row_t * 8 + i;
            sidx[row_t * 8 + i]   = bidx[i];
            out_idx_f[m * GV + g] = (float)bidx[i];
        }
    }
    __syncthreads();

    // fused quantize + loss
    const float* cbg = cb + (size_t)g * KV * DV;
    float lacc = 0.f;
    #pragma unroll
    for (int i = 0; i < 16; i++) {
        int u = tid + i * 256;
        int m  = u >> 5;
        int k4 = u & 31;
        int idx = sidx[m];
        const float4 xv = *(const float4*)(x + (size_t)(m0 + m) * (GV * DV) + g * DV + k4 * 4);
        const float4 qv = __ldg((const float4*)(cbg + (size_t)idx * DV + k4 * 4));
        float4 o;
        o.x = __fadd_rn(xv.x, __fsub_rn(qv.x, xv.x));
        o.y = __fadd_rn(xv.y, __fsub_rn(qv.y, xv.y));
        o.z = __fadd_rn(xv.z, __fsub_rn(qv.z, xv.z));
        o.w = __fadd_rn(xv.w, __fsub_rn(qv.w, xv.w));
        *(float4*)(outq + (size_t)(m0 + m) * (GV * DV) + g * DV + k4 * 4) = o;
        float d = __fsub_rn(xv.x, qv.x); lacc = fmaf(d, d, lacc);
        d = __fsub_rn(xv.y, qv.y); lacc = fmaf(d, d, lacc);
        d = __fsub_rn(xv.z, qv.z); lacc = fmaf(d, d, lacc);
        d = __fsub_rn(xv.w, qv.w); lacc = fmaf(d, d, lacc);
    }
    #pragma unroll
    for (int o = 16; o > 0; o >>= 1) lacc += __shfl_xor_sync(0xffffffffu, lacc, o);
    if ((tid & 31) == 0) wsum[tid >> 5] = lacc;
    __syncthreads();
    if (tid == 0) {
        double t = 0.0;
        #pragma unroll
        for (int i = 0; i < 8; i++) t += (double)wsum[i];
        atomicAdd(&g_loss, t);
        __threadfence();
        unsigned int done = atomicAdd(&g_cnt, 1u);
        if (done == (unsigned int)(gridDim.x * gridDim.y) - 1u) {
            float L = (float)(g_loss * (1.0 / (double)QN));
            losses[0] = L;
            losses[1] = L;
        }
    }
}

extern "C" void kernel_launch(void* const* d_in, const int* in_sizes, int n_in,
                              void* d_out, int out_size) {
    (void)in_sizes; (void)n_in; (void)out_size;
    const float* x  = (const float*)d_in[0];
    const float* cb = (const float*)d_in[1];
    float* out    = (float*)d_out;
    float* outq   = out;
    float* losses = out + QN;
    float* outidx = out + QN + 2;

    k_prep<<<256, 256>>>(cb);
    cudaFuncSetAttribute(k_main, cudaFuncAttributeMaxDynamicSharedMemorySize, SM_TOTAL);
    k_main<<<dim3(MV / 128, GV), 256, SM_TOTAL>>>(x, cb, outq, losses, outidx);
}